// round 2
// baseline (speedup 1.0000x reference)
#include <cuda_runtime.h>

#define BATCH  4
#define NSEQ   2048
#define DMODEL 1024
#define NH     16
#define DKH    64
#define BH     (BATCH*NH)

// Scratch (device globals: allocation-free per harness rules)
__device__ float g_qh[(size_t)BH * NSEQ * DKH];   // [B,H,N,dk]
__device__ float g_kh[(size_t)BH * NSEQ * DKH];
__device__ float g_vh[(size_t)BH * NSEQ * DKH];
__device__ float g_o [(size_t)BATCH * NSEQ * DMODEL]; // [B,N,H*dv]

// ---------------------------------------------------------------------------
// Projection GEMM: qh[b,h,n,k] = sum_d q[b,n,d] * w[h,d,k]
// M=8192 (b*N+n), Ncol=1024 (h*64+k), K=1024. 128x128x8 tile, 8x8 micro.
// gridDim.z selects q/k/v.
// ---------------------------------------------------------------------------
__global__ __launch_bounds__(256) void proj_gemm(
    const float* __restrict__ qin, const float* __restrict__ kin,
    const float* __restrict__ vin,
    const float* __restrict__ wq,  const float* __restrict__ wk,
    const float* __restrict__ wv)
{
    const float* A; const float* W; float* C;
    if (blockIdx.z == 0)      { A = qin; W = wq; C = g_qh; }
    else if (blockIdx.z == 1) { A = kin; W = wk; C = g_kh; }
    else                      { A = vin; W = wv; C = g_vh; }

    __shared__ float As[8][132];   // [k][m] transposed, pad 4 -> conflict-free
    __shared__ float Bs[8][128];   // [k][n]

    const int tid  = threadIdx.x;
    const int row0 = blockIdx.x * 128;
    const int col0 = blockIdx.y * 128;
    const int ty = tid >> 4, tx = tid & 15;

    const int arow = tid >> 1;
    const int acg  = (tid & 1) * 4;
    const int brow = tid >> 5;
    const int bcol = (tid & 31) * 4;

    const int   c     = col0 + bcol;
    const float* wbase = W + (size_t)(c >> 6) * (DMODEL * DKH) + (c & 63);
    const float* abase = A + (size_t)(row0 + arow) * DMODEL + acg;

    float acc[8][8];
    #pragma unroll
    for (int i = 0; i < 8; i++)
        #pragma unroll
        for (int j = 0; j < 8; j++) acc[i][j] = 0.f;

    for (int k0 = 0; k0 < DMODEL; k0 += 8) {
        float4 av = *(const float4*)(abase + k0);
        float4 bv = *(const float4*)(wbase + (size_t)(k0 + brow) * DKH);
        __syncthreads();
        As[acg + 0][arow] = av.x;
        As[acg + 1][arow] = av.y;
        As[acg + 2][arow] = av.z;
        As[acg + 3][arow] = av.w;
        *(float4*)&Bs[brow][bcol] = bv;
        __syncthreads();
        #pragma unroll
        for (int kk = 0; kk < 8; kk++) {
            float a[8], b[8];
            *(float4*)&a[0] = *(const float4*)&As[kk][ty * 8];
            *(float4*)&a[4] = *(const float4*)&As[kk][ty * 8 + 4];
            *(float4*)&b[0] = *(const float4*)&Bs[kk][tx * 8];
            *(float4*)&b[4] = *(const float4*)&Bs[kk][tx * 8 + 4];
            #pragma unroll
            for (int i = 0; i < 8; i++)
                #pragma unroll
                for (int j = 0; j < 8; j++) acc[i][j] += a[i] * b[j];
        }
    }

    #pragma unroll
    for (int i = 0; i < 8; i++) {
        const int r  = row0 + ty * 8 + i;
        const int bb = r >> 11;
        const int n  = r & (NSEQ - 1);
        #pragma unroll
        for (int jc = 0; jc < 8; jc += 4) {
            const int cc = col0 + tx * 8 + jc;
            const int h  = cc >> 6;
            const int kk = cc & 63;
            float4 v4 = make_float4(acc[i][jc], acc[i][jc+1], acc[i][jc+2], acc[i][jc+3]);
            *(float4*)&C[(((size_t)bb * NH + h) * NSEQ + n) * DKH + kk] = v4;
        }
    }
}

// ---------------------------------------------------------------------------
// Causal flash attention, fp32. One CTA = one (b,h) x 64-query block.
// 64x64 tiles, 256 threads, 4x4 micro-tile. P aliases the K smem buffer.
// ---------------------------------------------------------------------------
__global__ void __launch_bounds__(256, 2) flash_attn()
{
    extern __shared__ float sm[];
    float* Qs = sm;                 // [64][64]
    float* Ks = sm + 64 * 64;       // [64][68]  (also reused as Ps [64][68])
    float* Vs = Ks + 64 * 68;       // [64][64]
    float* Ps = Ks;

    const int tid = threadIdx.x;
    const int ty = tid >> 4, tx = tid & 15;
    const int r0 = ty * 4, c0 = tx * 4;
    const int qb = blockIdx.x, bh = blockIdx.y;
    const int q0 = qb * 64;
    const size_t base = (size_t)bh * NSEQ * DKH;

    #pragma unroll
    for (int it = 0; it < 4; it++) {
        int s = tid + it * 256;
        int row = s >> 4, d4 = (s & 15) * 4;
        *(float4*)&Qs[row * 64 + d4] =
            *(const float4*)&g_qh[base + (size_t)(q0 + row) * DKH + d4];
    }

    float O[4][4];
    float m[4], l[4];
    #pragma unroll
    for (int i = 0; i < 4; i++) {
        m[i] = -1e30f; l[i] = 0.f;
        #pragma unroll
        for (int j = 0; j < 4; j++) O[i][j] = 0.f;
    }

    for (int j = 0; j <= qb; j++) {
        const int k0 = j * 64;
        __syncthreads();   // prior-iter P/V reads done before overwrite
        #pragma unroll
        for (int it = 0; it < 4; it++) {
            int s = tid + it * 256;
            int row = s >> 4, d4 = (s & 15) * 4;
            *(float4*)&Ks[row * 68 + d4] =
                *(const float4*)&g_kh[base + (size_t)(k0 + row) * DKH + d4];
            *(float4*)&Vs[row * 64 + d4] =
                *(const float4*)&g_vh[base + (size_t)(k0 + row) * DKH + d4];
        }
        __syncthreads();

        float S[4][4];
        #pragma unroll
        for (int i = 0; i < 4; i++)
            #pragma unroll
            for (int jj = 0; jj < 4; jj++) S[i][jj] = 0.f;

        #pragma unroll
        for (int d = 0; d < 64; d += 4) {
            float4 qv[4], kv[4];
            #pragma unroll
            for (int i = 0; i < 4; i++)
                qv[i] = *(const float4*)&Qs[(r0 + i) * 64 + d];
            #pragma unroll
            for (int jj = 0; jj < 4; jj++)
                kv[jj] = *(const float4*)&Ks[(c0 + jj) * 68 + d];
            #pragma unroll
            for (int i = 0; i < 4; i++)
                #pragma unroll
                for (int jj = 0; jj < 4; jj++) {
                    S[i][jj] += qv[i].x * kv[jj].x;
                    S[i][jj] += qv[i].y * kv[jj].y;
                    S[i][jj] += qv[i].z * kv[jj].z;
                    S[i][jj] += qv[i].w * kv[jj].w;
                }
        }

        float p[4][4];
        const bool diag = (j == qb);
        #pragma unroll
        for (int i = 0; i < 4; i++) {
            #pragma unroll
            for (int jj = 0; jj < 4; jj++) {
                float t = S[i][jj] * 0.125f;          // 1/sqrt(64)
                if (diag && (c0 + jj > r0 + i)) t = -1e30f;
                p[i][jj] = t;
            }
            float rm = fmaxf(fmaxf(p[i][0], p[i][1]), fmaxf(p[i][2], p[i][3]));
            rm = fmaxf(rm, __shfl_xor_sync(0xffffffffu, rm, 1));
            rm = fmaxf(rm, __shfl_xor_sync(0xffffffffu, rm, 2));
            rm = fmaxf(rm, __shfl_xor_sync(0xffffffffu, rm, 4));
            rm = fmaxf(rm, __shfl_xor_sync(0xffffffffu, rm, 8));
            float mn = fmaxf(m[i], rm);
            float alpha = __expf(m[i] - mn);
            m[i] = mn;
            float rs = 0.f;
            #pragma unroll
            for (int jj = 0; jj < 4; jj++) {
                float e = __expf(p[i][jj] - mn);
                p[i][jj] = e;
                rs += e;
            }
            rs += __shfl_xor_sync(0xffffffffu, rs, 1);
            rs += __shfl_xor_sync(0xffffffffu, rs, 2);
            rs += __shfl_xor_sync(0xffffffffu, rs, 4);
            rs += __shfl_xor_sync(0xffffffffu, rs, 8);
            l[i] = l[i] * alpha + rs;
            #pragma unroll
            for (int jj = 0; jj < 4; jj++) O[i][jj] *= alpha;
        }

        __syncthreads();   // everyone finished reading Ks before aliasing as Ps
        #pragma unroll
        for (int i = 0; i < 4; i++)
            *(float4*)&Ps[(r0 + i) * 68 + c0] =
                make_float4(p[i][0], p[i][1], p[i][2], p[i][3]);
        __syncthreads();

        #pragma unroll 8
        for (int cc = 0; cc < 64; cc++) {
            float4 vv = *(const float4*)&Vs[cc * 64 + c0];
            float a0 = Ps[(r0 + 0) * 68 + cc];
            float a1 = Ps[(r0 + 1) * 68 + cc];
            float a2 = Ps[(r0 + 2) * 68 + cc];
            float a3 = Ps[(r0 + 3) * 68 + cc];
            O[0][0] += a0 * vv.x; O[0][1] += a0 * vv.y; O[0][2] += a0 * vv.z; O[0][3] += a0 * vv.w;
            O[1][0] += a1 * vv.x; O[1][1] += a1 * vv.y; O[1][2] += a1 * vv.z; O[1][3] += a1 * vv.w;
            O[2][0] += a2 * vv.x; O[2][1] += a2 * vv.y; O[2][2] += a2 * vv.z; O[2][3] += a2 * vv.w;
            O[3][0] += a3 * vv.x; O[3][1] += a3 * vv.y; O[3][2] += a3 * vv.z; O[3][3] += a3 * vv.w;
        }
    }

    const int bb = bh >> 4, h = bh & 15;
    #pragma unroll
    for (int i = 0; i < 4; i++) {
        const float inv = 1.f / l[i];
        const int r = q0 + r0 + i;
        float4 v4 = make_float4(O[i][0]*inv, O[i][1]*inv, O[i][2]*inv, O[i][3]*inv);
        *(float4*)&g_o[((size_t)bb * NSEQ + r) * DMODEL + h * DKH + c0] = v4;
    }
}

// ---------------------------------------------------------------------------
// Output GEMM: out[8192,1024] = g_o[8192,1024] @ w_o[1024,1024] (row-major)
// ---------------------------------------------------------------------------
__global__ __launch_bounds__(256) void out_gemm(
    const float* __restrict__ W, float* __restrict__ out)
{
    __shared__ float As[8][132];
    __shared__ float Bs[8][128];

    const int tid  = threadIdx.x;
    const int row0 = blockIdx.x * 128;
    const int col0 = blockIdx.y * 128;
    const int ty = tid >> 4, tx = tid & 15;

    const int arow = tid >> 1;
    const int acg  = (tid & 1) * 4;
    const int brow = tid >> 5;
    const int bcol = (tid & 31) * 4;

    const float* abase = g_o + (size_t)(row0 + arow) * DMODEL + acg;
    const float* wbase = W + col0 + bcol;

    float acc[8][8];
    #pragma unroll
    for (int i = 0; i < 8; i++)
        #pragma unroll
        for (int j = 0; j < 8; j++) acc[i][j] = 0.f;

    for (int k0 = 0; k0 < DMODEL; k0 += 8) {
        float4 av = *(const float4*)(abase + k0);
        float4 bv = *(const float4*)(wbase + (size_t)(k0 + brow) * DMODEL);
        __syncthreads();
        As[acg + 0][arow] = av.x;
        As[acg + 1][arow] = av.y;
        As[acg + 2][arow] = av.z;
        As[acg + 3][arow] = av.w;
        *(float4*)&Bs[brow][bcol] = bv;
        __syncthreads();
        #pragma unroll
        for (int kk = 0; kk < 8; kk++) {
            float a[8], b[8];
            *(float4*)&a[0] = *(const float4*)&As[kk][ty * 8];
            *(float4*)&a[4] = *(const float4*)&As[kk][ty * 8 + 4];
            *(float4*)&b[0] = *(const float4*)&Bs[kk][tx * 8];
            *(float4*)&b[4] = *(const float4*)&Bs[kk][tx * 8 + 4];
            #pragma unroll
            for (int i = 0; i < 8; i++)
                #pragma unroll
                for (int j = 0; j < 8; j++) acc[i][j] += a[i] * b[j];
        }
    }

    #pragma unroll
    for (int i = 0; i < 8; i++) {
        const int r = row0 + ty * 8 + i;
        #pragma unroll
        for (int jc = 0; jc < 8; jc += 4) {
            const int cc = col0 + tx * 8 + jc;
            float4 v4 = make_float4(acc[i][jc], acc[i][jc+1], acc[i][jc+2], acc[i][jc+3]);
            *(float4*)&out[(size_t)r * DMODEL + cc] = v4;
        }
    }
}

// ---------------------------------------------------------------------------
extern "C" void kernel_launch(void* const* d_in, const int* in_sizes, int n_in,
                              void* d_out, int out_size)
{
    (void)in_sizes; (void)n_in; (void)out_size;
    const float* q   = (const float*)d_in[0];
    const float* k   = (const float*)d_in[1];
    const float* v   = (const float*)d_in[2];
    const float* w_q = (const float*)d_in[3];
    const float* w_k = (const float*)d_in[4];
    const float* w_v = (const float*)d_in[5];
    const float* w_o = (const float*)d_in[6];
    float* out = (float*)d_out;

    const int flash_smem = (64*64 + 64*68 + 64*64) * (int)sizeof(float); // 50176
    cudaFuncSetAttribute(flash_attn, cudaFuncAttributeMaxDynamicSharedMemorySize,
                         flash_smem);

    dim3 gproj(8192 / 128, 1024 / 128, 3);
    proj_gemm<<<gproj, 256>>>(q, k, v, w_q, w_k, w_v);

    dim3 gflash(NSEQ / 64, BH);
    flash_attn<<<gflash, 256, flash_smem>>>();

    dim3 gout(8192 / 128, 1024 / 128);
    out_gemm<<<gout, 256>>>(w_o, out);
}

// round 3
// speedup vs baseline: 1.9972x; 1.9972x over previous
#include <cuda_runtime.h>
#include <cuda_bf16.h>

#define NSEQ 2048
typedef unsigned uint_t;

// ---------------- device scratch (allocation-free) ----------------
__device__ __align__(16) __nv_bfloat16 g_qh[3][(size_t)64*NSEQ*64];
__device__ __align__(16) __nv_bfloat16 g_kh[3][(size_t)64*NSEQ*64];
__device__ __align__(16) __nv_bfloat16 g_vh[2][(size_t)64*NSEQ*64];
__device__ __align__(16) __nv_bfloat16 g_vt[2][(size_t)64*64*NSEQ];
__device__ __align__(16) __nv_bfloat16 g_wq[3][1024*1024];
__device__ __align__(16) __nv_bfloat16 g_wk[3][1024*1024];
__device__ __align__(16) __nv_bfloat16 g_wv[2][1024*1024];
__device__ __align__(16) __nv_bfloat16 g_wo[2][1024*1024];
__device__ __align__(16) float g_ao[(size_t)8192*1024];

// ---------------- helpers ----------------
__device__ __forceinline__ uint_t pk(float x, float y){
    __nv_bfloat162 t = __floats2bfloat162_rn(x, y);
    return *(uint_t*)&t;
}
__device__ __forceinline__ void sp(float x, float y, uint_t& h, uint_t& m,
                                   uint_t& l, bool three){
    float hx = __bfloat162float(__float2bfloat16_rn(x));
    float hy = __bfloat162float(__float2bfloat16_rn(y));
    float rx = x - hx, ry = y - hy;
    h = pk(hx, hy); m = pk(rx, ry);
    if (three) {
        float mx = __bfloat162float(__float2bfloat16_rn(rx));
        float my = __bfloat162float(__float2bfloat16_rn(ry));
        l = pk(rx - mx, ry - my);
    } else l = 0u;
}
__device__ __forceinline__ void mma4(float (&d)[4], const uint_t (&a)[4],
                                     uint_t b0, uint_t b1){
    asm volatile(
      "mma.sync.aligned.m16n8k16.row.col.f32.bf16.bf16.f32 "
      "{%0,%1,%2,%3}, {%4,%5,%6,%7}, {%8,%9}, {%0,%1,%2,%3};\n"
      : "+f"(d[0]), "+f"(d[1]), "+f"(d[2]), "+f"(d[3])
      : "r"(a[0]), "r"(a[1]), "r"(a[2]), "r"(a[3]), "r"(b0), "r"(b1));
}

// ---------------- weight prep (transpose + split) ----------------
// w_q/w_k [16][1024][64] -> [h*64+c][1024], 3 levels
__global__ __launch_bounds__(256) void prep_wqk(
    const float* __restrict__ wq, const float* __restrict__ wk)
{
    __shared__ float T[32][33];
    const int z = blockIdx.z, h = z & 15;
    const float* W = (z < 16 ? wq : wk) + (size_t)h * 65536;
    __nv_bfloat16* O0 = (z<16 ? g_wq[0] : g_wk[0]) + (size_t)h*64*1024;
    __nv_bfloat16* O1 = (z<16 ? g_wq[1] : g_wk[1]) + (size_t)h*64*1024;
    __nv_bfloat16* O2 = (z<16 ? g_wq[2] : g_wk[2]) + (size_t)h*64*1024;
    const int c0 = blockIdx.x*32, d0 = blockIdx.y*32;
    const int tx = threadIdx.x, ty = threadIdx.y;
    #pragma unroll
    for (int i = 0; i < 4; i++)
        T[ty+i*8][tx] = W[(size_t)(d0+ty+i*8)*64 + c0+tx];
    __syncthreads();
    #pragma unroll
    for (int i = 0; i < 4; i++) {
        float v = T[tx][ty+i*8];
        float hv = __bfloat162float(__float2bfloat16_rn(v));
        float r = v - hv;
        float mv = __bfloat162float(__float2bfloat16_rn(r));
        size_t idx = (size_t)(c0+ty+i*8)*1024 + d0+tx;
        O0[idx] = __float2bfloat16_rn(hv);
        O1[idx] = __float2bfloat16_rn(r);
        O2[idx] = __float2bfloat16_rn(r - mv);
    }
}
// w_v [16][1024][64] -> transposed 2 levels
__global__ __launch_bounds__(256) void prep_wv(const float* __restrict__ wv)
{
    __shared__ float T[32][33];
    const int h = blockIdx.z;
    const float* W = wv + (size_t)h * 65536;
    __nv_bfloat16* O0 = g_wv[0] + (size_t)h*64*1024;
    __nv_bfloat16* O1 = g_wv[1] + (size_t)h*64*1024;
    const int c0 = blockIdx.x*32, d0 = blockIdx.y*32;
    const int tx = threadIdx.x, ty = threadIdx.y;
    #pragma unroll
    for (int i = 0; i < 4; i++)
        T[ty+i*8][tx] = W[(size_t)(d0+ty+i*8)*64 + c0+tx];
    __syncthreads();
    #pragma unroll
    for (int i = 0; i < 4; i++) {
        float v = T[tx][ty+i*8];
        float hv = __bfloat162float(__float2bfloat16_rn(v));
        size_t idx = (size_t)(c0+ty+i*8)*1024 + d0+tx;
        O0[idx] = __float2bfloat16_rn(hv);
        O1[idx] = __float2bfloat16_rn(v - hv);
    }
}
// w_o [1024][1024] -> transposed 2 levels
__global__ __launch_bounds__(256) void prep_wo(const float* __restrict__ W)
{
    __shared__ float T[32][33];
    const int n0 = blockIdx.x*32, k0 = blockIdx.y*32;
    const int tx = threadIdx.x, ty = threadIdx.y;
    #pragma unroll
    for (int i = 0; i < 4; i++)
        T[ty+i*8][tx] = W[(size_t)(k0+ty+i*8)*1024 + n0+tx];
    __syncthreads();
    #pragma unroll
    for (int i = 0; i < 4; i++) {
        float v = T[tx][ty+i*8];
        float hv = __bfloat162float(__float2bfloat16_rn(v));
        size_t idx = (size_t)(n0+ty+i*8)*1024 + k0+tx;
        g_wo[0][idx] = __float2bfloat16_rn(hv);
        g_wo[1][idx] = __float2bfloat16_rn(v - hv);
    }
}

// ---------------- generic split-bf16 GEMM tile (128x128, k-step 16) ------
// A fp32 [8192][1024]; B levels [1024 n][1024 k]. NLV=3 -> 6 passes, 2 -> 3.
template<int NLV>
__device__ __forceinline__ void gemm_tile(
    const float* __restrict__ A,
    const __nv_bfloat16* __restrict__ B0,
    const __nv_bfloat16* __restrict__ B1,
    const __nv_bfloat16* __restrict__ B2,
    int row0, int col0, __nv_bfloat16* SM, float (&acc)[4][4][4])
{
    constexpr int NP = (NLV == 3) ? 6 : 3;
    const int PA[6] = {0,0,1,0,2,1}, PB[6] = {0,1,0,2,0,1};
    const __nv_bfloat16* Bp[3] = {B0, B1, B2};
    __nv_bfloat16* SB = SM + NLV*3072;

    const int tid = threadIdx.x, w = tid>>5, lane = tid&31;
    const int wm = w>>2, wn = w&3, g = lane>>2, tg = lane&3;
    const int srow = tid>>1, skb = (tid&1)*8;
    const float* Ap = A + (size_t)(row0+srow)*1024 + skb;
    const size_t boff = (size_t)(col0+srow)*1024 + skb;
    const int soff = srow*24 + skb;

    #pragma unroll
    for (int a = 0; a < 4; a++)
        #pragma unroll
        for (int b = 0; b < 4; b++)
            #pragma unroll
            for (int c = 0; c < 4; c++) acc[a][b][c] = 0.f;

    float4 a0 = *(const float4*)Ap, a1 = *(const float4*)(Ap+4);
    uint4 bv[NLV];
    #pragma unroll
    for (int lv = 0; lv < NLV; lv++) bv[lv] = *(const uint4*)(Bp[lv]+boff);

    #pragma unroll 1
    for (int k0 = 0; k0 < 1024; k0 += 16) {
        {   // store staged data
            uint_t h[4], m[4], l[4];
            sp(a0.x,a0.y,h[0],m[0],l[0],NLV==3); sp(a0.z,a0.w,h[1],m[1],l[1],NLV==3);
            sp(a1.x,a1.y,h[2],m[2],l[2],NLV==3); sp(a1.z,a1.w,h[3],m[3],l[3],NLV==3);
            *(uint4*)&SM[soff]      = make_uint4(h[0],h[1],h[2],h[3]);
            *(uint4*)&SM[3072+soff] = make_uint4(m[0],m[1],m[2],m[3]);
            if (NLV == 3) *(uint4*)&SM[6144+soff] = make_uint4(l[0],l[1],l[2],l[3]);
            #pragma unroll
            for (int lv = 0; lv < NLV; lv++)
                *(uint4*)&SB[lv*3072+soff] = bv[lv];
        }
        __syncthreads();
        const bool more = (k0 + 16) < 1024;
        if (more) {
            a0 = *(const float4*)(Ap+k0+16); a1 = *(const float4*)(Ap+k0+20);
            #pragma unroll
            for (int lv = 0; lv < NLV; lv++)
                bv[lv] = *(const uint4*)(Bp[lv]+boff+k0+16);
        }
        const int kc = tg*2;
        uint_t bf[NLV][4][2];
        #pragma unroll
        for (int nf = 0; nf < 4; nf++) {
            int nro = (wn*32+nf*8+g)*24 + kc;
            #pragma unroll
            for (int lv = 0; lv < NLV; lv++) {
                bf[lv][nf][0] = *(const uint_t*)&SB[lv*3072+nro];
                bf[lv][nf][1] = *(const uint_t*)&SB[lv*3072+nro+8];
            }
        }
        #pragma unroll
        for (int mf = 0; mf < 4; mf++) {
            int mro = (wm*64+mf*16+g)*24 + kc;
            uint_t af[NLV][4];
            #pragma unroll
            for (int lv = 0; lv < NLV; lv++) {
                const __nv_bfloat16* sa = SM + lv*3072;
                af[lv][0] = *(const uint_t*)&sa[mro];
                af[lv][1] = *(const uint_t*)&sa[mro+192];
                af[lv][2] = *(const uint_t*)&sa[mro+8];
                af[lv][3] = *(const uint_t*)&sa[mro+200];
            }
            #pragma unroll
            for (int nf = 0; nf < 4; nf++)
                #pragma unroll
                for (int p = 0; p < NP; p++)
                    mma4(acc[mf][nf], af[PA[p]], bf[PB[p]][nf][0], bf[PB[p]][nf][1]);
        }
        __syncthreads();
    }
}

// ---------------- projection kernels ----------------
__global__ __launch_bounds__(256) void proj_qk(
    const float* __restrict__ q, const float* __restrict__ k)
{
    __shared__ __nv_bfloat16 SM[6*3072];
    const int z = blockIdx.z;
    const float* A = z ? k : q;
    float acc[4][4][4];
    const int row0 = blockIdx.x*128, col0 = blockIdx.y*128;
    gemm_tile<3>(A, z ? g_wk[0] : g_wq[0], z ? g_wk[1] : g_wq[1],
                 z ? g_wk[2] : g_wq[2], row0, col0, SM, acc);
    __nv_bfloat16* O0 = z ? g_kh[0] : g_qh[0];
    __nv_bfloat16* O1 = z ? g_kh[1] : g_qh[1];
    __nv_bfloat16* O2 = z ? g_kh[2] : g_qh[2];
    const int tid = threadIdx.x, w = tid>>5, lane = tid&31;
    const int wm = w>>2, wn = w&3, g = lane>>2, tg = lane&3;
    #pragma unroll
    for (int mf = 0; mf < 4; mf++) {
        int r = row0 + wm*64 + mf*16 + g;
        int b = r >> 11, n = r & (NSEQ-1);
        #pragma unroll
        for (int nf = 0; nf < 4; nf++) {
            int c = col0 + wn*32 + nf*8 + tg*2;
            size_t idx = (((size_t)(b*16 + (c>>6)))*NSEQ + n)*64 + (c&63);
            uint_t h, m, l;
            sp(acc[mf][nf][0], acc[mf][nf][1], h, m, l, true);
            *(uint_t*)&O0[idx] = h; *(uint_t*)&O1[idx] = m; *(uint_t*)&O2[idx] = l;
            sp(acc[mf][nf][2], acc[mf][nf][3], h, m, l, true);
            *(uint_t*)&O0[idx+512] = h; *(uint_t*)&O1[idx+512] = m;
            *(uint_t*)&O2[idx+512] = l;
        }
    }
}

__global__ __launch_bounds__(256) void proj_v(const float* __restrict__ v)
{
    __shared__ __nv_bfloat16 SM[4*3072];
    float acc[4][4][4];
    const int row0 = blockIdx.x*128, col0 = blockIdx.y*128;
    gemm_tile<2>(v, g_wv[0], g_wv[1], g_wv[1], row0, col0, SM, acc);
    const int tid = threadIdx.x, w = tid>>5, lane = tid&31;
    const int wm = w>>2, wn = w&3, g = lane>>2, tg = lane&3;
    #pragma unroll
    for (int mf = 0; mf < 4; mf++) {
        int r = row0 + wm*64 + mf*16 + g;
        int b = r >> 11, n = r & (NSEQ-1);
        #pragma unroll
        for (int nf = 0; nf < 4; nf++) {
            int c = col0 + wn*32 + nf*8 + tg*2;
            size_t idx = (((size_t)(b*16 + (c>>6)))*NSEQ + n)*64 + (c&63);
            uint_t h, m, l;
            sp(acc[mf][nf][0], acc[mf][nf][1], h, m, l, false);
            *(uint_t*)&g_vh[0][idx] = h; *(uint_t*)&g_vh[1][idx] = m;
            sp(acc[mf][nf][2], acc[mf][nf][3], h, m, l, false);
            *(uint_t*)&g_vh[0][idx+512] = h; *(uint_t*)&g_vh[1][idx+512] = m;
        }
    }
}

// ---------------- V transpose: [bh][n][64] -> [bh][64][n] ----------------
__global__ __launch_bounds__(256) void transpose_vh()
{
    __shared__ __nv_bfloat16 T[64][72];
    const int tid = threadIdx.x;
    const int n0 = blockIdx.x*64, bh = blockIdx.y;
    #pragma unroll
    for (int pass = 0; pass < 2; pass++) {
        const __nv_bfloat16* src = g_vh[pass];
        __nv_bfloat16* dst = g_vt[pass];
        int n = tid >> 2, d0 = (tid & 3)*16;
        size_t sidx = ((size_t)bh*NSEQ + n0+n)*64 + d0;
        *(uint4*)&T[n][d0]   = *(const uint4*)&src[sidx];
        *(uint4*)&T[n][d0+8] = *(const uint4*)&src[sidx+8];
        __syncthreads();
        int d = tid >> 2, nn0 = (tid & 3)*16;
        uint_t r[8];
        #pragma unroll
        for (int j = 0; j < 8; j++) {
            __nv_bfloat162 t;
            t.x = T[nn0+2*j][d]; t.y = T[nn0+2*j+1][d];
            r[j] = *(uint_t*)&t;
        }
        size_t didx = ((size_t)bh*64 + d)*NSEQ + n0 + nn0;
        *(uint4*)&dst[didx]   = make_uint4(r[0],r[1],r[2],r[3]);
        *(uint4*)&dst[didx+8] = make_uint4(r[4],r[5],r[6],r[7]);
        __syncthreads();
    }
}

// ---------------- flash attention ----------------
__global__ __launch_bounds__(256) void flash_attn()
{
    extern __shared__ __nv_bfloat16 sm[];
    __nv_bfloat16* Kh = sm;            // 64*72 each
    __nv_bfloat16* Km = sm + 4608;
    __nv_bfloat16* Kl = sm + 9216;
    __nv_bfloat16* Vh = sm + 13824;
    __nv_bfloat16* Vl = sm + 18432;

    const int tid = threadIdx.x, w = tid>>5, lane = tid&31;
    const int g = lane>>2, tg = lane&3;
    const int qb = blockIdx.x, bh = blockIdx.y;
    const int q0 = qb*128;
    const int row0 = q0 + w*16 + g;
    const size_t base = (size_t)bh*NSEQ*64;

    // stage Q per warp through smem (overlaps Kh/Km region), extract frags
    uint_t qf[3][4][4];
    {
        __nv_bfloat16* qs = sm + w*1152;
        #pragma unroll
        for (int lv = 0; lv < 3; lv++) {
            const __nv_bfloat16* Qs = g_qh[lv];
            #pragma unroll
            for (int it = 0; it < 4; it++) {
                int idx = it*32 + lane;
                int r = idx >> 3, c8 = (idx & 7)*8;
                *(uint4*)&qs[r*72 + c8] =
                    *(const uint4*)&Qs[base + (size_t)(q0+w*16+r)*64 + c8];
            }
            __syncwarp();
            #pragma unroll
            for (int s = 0; s < 4; s++) {
                int kc = s*16 + tg*2;
                qf[lv][s][0] = *(const uint_t*)&qs[g*72+kc];
                qf[lv][s][1] = *(const uint_t*)&qs[(g+8)*72+kc];
                qf[lv][s][2] = *(const uint_t*)&qs[g*72+kc+8];
                qf[lv][s][3] = *(const uint_t*)&qs[(g+8)*72+kc+8];
            }
            __syncwarp();
        }
    }
    __syncthreads();

    float O[8][4];
    #pragma unroll
    for (int nf = 0; nf < 8; nf++)
        #pragma unroll
        for (int e = 0; e < 4; e++) O[nf][e] = 0.f;
    float m0 = -1e30f, m1 = -1e30f, l0 = 0.f, l1 = 0.f;

    const int ntiles = 2*qb + 2;
    #pragma unroll 1
    for (int kt = 0; kt < ntiles; kt++) {
        {
            int key = tid >> 2, off = (tid & 3)*16;
            size_t si = base + (size_t)(kt*64+key)*64 + off;
            *(uint4*)&Kh[key*72+off]   = *(const uint4*)&g_kh[0][si];
            *(uint4*)&Kh[key*72+off+8] = *(const uint4*)&g_kh[0][si+8];
            *(uint4*)&Km[key*72+off]   = *(const uint4*)&g_kh[1][si];
            *(uint4*)&Km[key*72+off+8] = *(const uint4*)&g_kh[1][si+8];
            *(uint4*)&Kl[key*72+off]   = *(const uint4*)&g_kh[2][si];
            *(uint4*)&Kl[key*72+off+8] = *(const uint4*)&g_kh[2][si+8];
            size_t vi = ((size_t)bh*64 + key)*NSEQ + kt*64 + off;
            *(uint4*)&Vh[key*72+off]   = *(const uint4*)&g_vt[0][vi];
            *(uint4*)&Vh[key*72+off+8] = *(const uint4*)&g_vt[0][vi+8];
            *(uint4*)&Vl[key*72+off]   = *(const uint4*)&g_vt[1][vi];
            *(uint4*)&Vl[key*72+off+8] = *(const uint4*)&g_vt[1][vi+8];
        }
        __syncthreads();

        if (!((kt == 2*qb+1) && (w < 4))) {
            float S[8][4];
            #pragma unroll
            for (int nf = 0; nf < 8; nf++)
                #pragma unroll
                for (int e = 0; e < 4; e++) S[nf][e] = 0.f;

            #pragma unroll
            for (int nf = 0; nf < 8; nf++) {
                int kr = (nf*8+g)*72;
                #pragma unroll
                for (int s = 0; s < 4; s++) {
                    int kc = s*16 + tg*2;
                    uint_t kh0 = *(const uint_t*)&Kh[kr+kc];
                    uint_t kh1 = *(const uint_t*)&Kh[kr+kc+8];
                    uint_t km0 = *(const uint_t*)&Km[kr+kc];
                    uint_t km1 = *(const uint_t*)&Km[kr+kc+8];
                    uint_t kl0 = *(const uint_t*)&Kl[kr+kc];
                    uint_t kl1 = *(const uint_t*)&Kl[kr+kc+8];
                    mma4(S[nf], qf[0][s], kh0, kh1);
                    mma4(S[nf], qf[0][s], km0, km1);
                    mma4(S[nf], qf[1][s], kh0, kh1);
                    mma4(S[nf], qf[0][s], kl0, kl1);
                    mma4(S[nf], qf[2][s], kh0, kh1);
                    mma4(S[nf], qf[1][s], km0, km1);
                }
            }

            const bool maskt = (kt >= 2*qb);
            float rmax0 = -1e30f, rmax1 = -1e30f;
            #pragma unroll
            for (int nf = 0; nf < 8; nf++) {
                int colb = kt*64 + nf*8 + tg*2;
                S[nf][0] *= 0.125f; S[nf][1] *= 0.125f;
                S[nf][2] *= 0.125f; S[nf][3] *= 0.125f;
                if (maskt) {
                    if (colb   > row0)   S[nf][0] = -1e30f;
                    if (colb+1 > row0)   S[nf][1] = -1e30f;
                    if (colb   > row0+8) S[nf][2] = -1e30f;
                    if (colb+1 > row0+8) S[nf][3] = -1e30f;
                }
                rmax0 = fmaxf(rmax0, fmaxf(S[nf][0], S[nf][1]));
                rmax1 = fmaxf(rmax1, fmaxf(S[nf][2], S[nf][3]));
            }
            rmax0 = fmaxf(rmax0, __shfl_xor_sync(~0u, rmax0, 1));
            rmax0 = fmaxf(rmax0, __shfl_xor_sync(~0u, rmax0, 2));
            rmax1 = fmaxf(rmax1, __shfl_xor_sync(~0u, rmax1, 1));
            rmax1 = fmaxf(rmax1, __shfl_xor_sync(~0u, rmax1, 2));
            float mn0 = fmaxf(m0, rmax0), mn1 = fmaxf(m1, rmax1);
            float a0 = __expf(m0 - mn0), a1 = __expf(m1 - mn1);
            m0 = mn0; m1 = mn1;
            float rs0 = 0.f, rs1 = 0.f;
            #pragma unroll
            for (int nf = 0; nf < 8; nf++) {
                S[nf][0] = __expf(S[nf][0]-mn0); rs0 += S[nf][0];
                S[nf][1] = __expf(S[nf][1]-mn0); rs0 += S[nf][1];
                S[nf][2] = __expf(S[nf][2]-mn1); rs1 += S[nf][2];
                S[nf][3] = __expf(S[nf][3]-mn1); rs1 += S[nf][3];
            }
            rs0 += __shfl_xor_sync(~0u, rs0, 1); rs0 += __shfl_xor_sync(~0u, rs0, 2);
            rs1 += __shfl_xor_sync(~0u, rs1, 1); rs1 += __shfl_xor_sync(~0u, rs1, 2);
            l0 = l0*a0 + rs0; l1 = l1*a1 + rs1;
            #pragma unroll
            for (int nf = 0; nf < 8; nf++) {
                O[nf][0] *= a0; O[nf][1] *= a0;
                O[nf][2] *= a1; O[nf][3] *= a1;
            }

            #pragma unroll
            for (int s = 0; s < 4; s++) {
                uint_t ph[4], pl[4], dum;
                sp(S[2*s][0],   S[2*s][1],   ph[0], pl[0], dum=0, false);
                sp(S[2*s][2],   S[2*s][3],   ph[1], pl[1], dum, false);
                sp(S[2*s+1][0], S[2*s+1][1], ph[2], pl[2], dum, false);
                sp(S[2*s+1][2], S[2*s+1][3], ph[3], pl[3], dum, false);
                #pragma unroll
                for (int nf = 0; nf < 8; nf++) {
                    int vr = (nf*8+g)*72, vc = s*16 + tg*2;
                    uint_t v0 = *(const uint_t*)&Vh[vr+vc];
                    uint_t v1 = *(const uint_t*)&Vh[vr+vc+8];
                    uint_t u0 = *(const uint_t*)&Vl[vr+vc];
                    uint_t u1 = *(const uint_t*)&Vl[vr+vc+8];
                    mma4(O[nf], ph, v0, v1);
                    mma4(O[nf], ph, u0, u1);
                    mma4(O[nf], pl, v0, v1);
                }
            }
        }
        __syncthreads();
    }

    const float inv0 = 1.f/l0, inv1 = 1.f/l1;
    const size_t or0 = ((size_t)(bh>>4)*NSEQ + row0)*1024 + (bh&15)*64;
    #pragma unroll
    for (int nf = 0; nf < 8; nf++) {
        int c = nf*8 + tg*2;
        *(float2*)&g_ao[or0 + c]        = make_float2(O[nf][0]*inv0, O[nf][1]*inv0);
        *(float2*)&g_ao[or0 + 8192 + c] = make_float2(O[nf][2]*inv1, O[nf][3]*inv1);
    }
}

// ---------------- output GEMM ----------------
__global__ __launch_bounds__(256) void out_gemm(float* __restrict__ out)
{
    __shared__ __nv_bfloat16 SM[4*3072];
    float acc[4][4][4];
    const int row0 = blockIdx.x*128, col0 = blockIdx.y*128;
    gemm_tile<2>(g_ao, g_wo[0], g_wo[1], g_wo[1], row0, col0, SM, acc);
    const int tid = threadIdx.x, w = tid>>5, lane = tid&31;
    const int wm = w>>2, wn = w&3, g = lane>>2, tg = lane&3;
    #pragma unroll
    for (int mf = 0; mf < 4; mf++) {
        int r = row0 + wm*64 + mf*16 + g;
        #pragma unroll
        for (int nf = 0; nf < 4; nf++) {
            int c = col0 + wn*32 + nf*8 + tg*2;
            *(float2*)&out[(size_t)r*1024 + c] =
                make_float2(acc[mf][nf][0], acc[mf][nf][1]);
            *(float2*)&out[(size_t)(r+8)*1024 + c] =
                make_float2(acc[mf][nf][2], acc[mf][nf][3]);
        }
    }
}

// ---------------- launch ----------------
extern "C" void kernel_launch(void* const* d_in, const int* in_sizes, int n_in,
                              void* d_out, int out_size)
{
    (void)in_sizes; (void)n_in; (void)out_size;
    const float* q   = (const float*)d_in[0];
    const float* k   = (const float*)d_in[1];
    const float* v   = (const float*)d_in[2];
    const float* w_q = (const float*)d_in[3];
    const float* w_k = (const float*)d_in[4];
    const float* w_v = (const float*)d_in[5];
    const float* w_o = (const float*)d_in[6];
    float* out = (float*)d_out;

    static int init = 0;
    if (!init) {
        cudaFuncSetAttribute(flash_attn,
            cudaFuncAttributeMaxDynamicSharedMemorySize, 46080);
        init = 1;
    }

    dim3 tb(32, 8);
    prep_wqk<<<dim3(2, 32, 32), tb>>>(w_q, w_k);
    prep_wv <<<dim3(2, 32, 16), tb>>>(w_v);
    prep_wo <<<dim3(32, 32), tb>>>(w_o);

    proj_qk<<<dim3(64, 8, 2), 256>>>(q, k);
    proj_v <<<dim3(64, 8), 256>>>(v);
    transpose_vh<<<dim3(32, 64), 256>>>();
    flash_attn<<<dim3(16, 64), 256, 46080>>>();
    out_gemm<<<dim3(64, 8), 256>>>(out);
}